// round 12
// baseline (speedup 1.0000x reference)
#include <cuda_runtime.h>
#include <cuda_fp16.h>
#include <math.h>

#define NV 786432
#define KS 5
#define EMAX (8 * NV)
#define SCAN_BLOCKS 192   // NV / 4096

// ---- static device scratch (no allocations allowed) ----
__device__ __half g_t1[(size_t)NV * 32];
__device__ __half g_t2[(size_t)NV * 32];
__device__ __half g_t3[(size_t)NV * 32];
__device__ __half g_t4[(size_t)NV * 32];
__device__ __half g_h [(size_t)NV * 32];
__device__ __half g_xh[(size_t)NV * 16];
__device__ int   g_deg[NV];          // zero at entry; finalize re-zeroes for next replay
__device__ int   g_excl[NV];
__device__ int   g_rowptr[NV + 1];
__device__ int   g_pos[NV];
__device__ int   g_bsum[SCAN_BLOCKS];
__device__ int2  g_edge[EMAX];       // (col, float_as_int(val)) interleaved

// ===========================================================================
// CSR build (4 kernels)
// ===========================================================================
__global__ void hist_kernel(const int* __restrict__ rows, int* __restrict__ deg, int nedges) {
    int e = blockIdx.x * blockDim.x + threadIdx.x;
    if (e < nedges) atomicAdd(deg + __ldg(rows + e), 1);
}

__global__ void scan_local_kernel(const int* __restrict__ deg, int* __restrict__ excl,
                                  int* __restrict__ bsum) {
    __shared__ int warp_sums[32];
    int t = threadIdx.x;
    int base = blockIdx.x * 4096 + t * 4;
    int4 d = *(const int4*)(deg + base);
    int tsum = d.x + d.y + d.z + d.w;
    int lane = t & 31, wid = t >> 5;
    int v = tsum;
#pragma unroll
    for (int o = 1; o < 32; o <<= 1) {
        int n = __shfl_up_sync(~0u, v, o);
        if (lane >= o) v += n;
    }
    if (lane == 31) warp_sums[wid] = v;
    __syncthreads();
    if (wid == 0) {
        int ws = warp_sums[lane];
#pragma unroll
        for (int o = 1; o < 32; o <<= 1) {
            int n = __shfl_up_sync(~0u, ws, o);
            if (lane >= o) ws += n;
        }
        warp_sums[lane] = ws;
    }
    __syncthreads();
    int warp_off = (wid == 0) ? 0 : warp_sums[wid - 1];
    int e0 = warp_off + v - tsum;
    excl[base + 0] = e0;
    excl[base + 1] = e0 + d.x;
    excl[base + 2] = e0 + d.x + d.y;
    excl[base + 3] = e0 + d.x + d.y + d.z;
    if (t == 0) bsum[blockIdx.x] = warp_sums[31];
}

__global__ void finalize_kernel(const int* __restrict__ excl, const int* __restrict__ bsum,
                                int* __restrict__ rowptr, int* __restrict__ pos,
                                int* __restrict__ deg, int nedges) {
    __shared__ int s[256];
    int t = threadIdx.x;
    s[t] = (t < SCAN_BLOCKS) ? bsum[t] : 0;
    __syncthreads();
#pragma unroll
    for (int o = 1; o < 256; o <<= 1) {
        int add = (t >= o) ? s[t - o] : 0;
        __syncthreads();
        s[t] += add;
        __syncthreads();
    }
    int i = blockIdx.x * 256 + t;
    if (i < NV) {
        int sb = i >> 12;
        int off = (sb == 0) ? 0 : s[sb - 1];
        int r = excl[i] + off;
        rowptr[i] = r;
        pos[i] = r;
        deg[i] = 0;
        if (i == 0) rowptr[NV] = nedges;
    }
}

__global__ void fill_kernel(const int* __restrict__ rows, const int* __restrict__ cols,
                            const float* __restrict__ vals, int* __restrict__ pos,
                            int2* __restrict__ edge, int nedges) {
    int e = blockIdx.x * blockDim.x + threadIdx.x;
    if (e >= nedges) return;
    int r = __ldg(rows + e);
    int p = atomicAdd(pos + r, 1);
    edge[p] = make_int2(__ldg(cols + e), __float_as_int(__ldg(vals + e)));
}

// x (fp32, 16 ch) -> half
__global__ void cvt_x_kernel(const float* __restrict__ x, __half* __restrict__ xh) {
    int i = blockIdx.x * blockDim.x + threadIdx.x;   // one per 8 elems
    if (i >= NV * 2) return;
    float4 a = ((const float4*)x)[i * 2];
    float4 b = ((const float4*)x)[i * 2 + 1];
    uint4 o;
    ((__half2*)&o)[0] = __floats2half2_rn(a.x, a.y);
    ((__half2*)&o)[1] = __floats2half2_rn(a.z, a.w);
    ((__half2*)&o)[2] = __floats2half2_rn(b.x, b.y);
    ((__half2*)&o)[3] = __floats2half2_rn(b.z, b.w);
    ((uint4*)xh)[i] = o;
}

// ===========================================================================
// Shuffle-SpMM (fp16 features, fp32 accumulate) with fused recurrence:
//   t[v,:] = scale * sum_j val_j * z[col_j,:]  -  (prev ? prev[v,:] : 0)
// LPR = FIN/8 lanes per row (one uint4 = 8 half per lane). Per 4-edge batch
// the LPR lanes of a row load DISTINCT edges (coalesced 32B) and exchange
// (col,w) via __shfl_sync: no SMEM staging, no __syncthreads, every warp
// fully independent. EPL = edges loaded per lane per batch.
// ===========================================================================
__device__ __forceinline__ void fma8(float* acc, uint4 zz, float w) {
    const __half2* hp = (const __half2*)&zz;
#pragma unroll
    for (int i = 0; i < 4; i++) {
        float2 f = __half22float2(hp[i]);
        acc[2 * i]     += w * f.x;
        acc[2 * i + 1] += w * f.y;
    }
}

template<int FIN>
__global__ void __launch_bounds__(256) spmm_kernel(
        const int* __restrict__ rowptr, const int2* __restrict__ edge,
        const __half* __restrict__ z, const __half* __restrict__ prev,
        float scale, __half* __restrict__ t) {
    constexpr int LPR = FIN / 8;       // lanes per row (32ch: 4, 16ch: 2)
    constexpr int EPL = 4 / LPR;       // edges per lane per batch
    int tid = blockIdx.x * 256 + threadIdx.x;
    int v  = tid / LPR;
    int f4 = tid % LPR;
    if (v >= NV) return;
    int lane = threadIdx.x & 31;
    int rowbase = lane & ~(LPR - 1);   // first lane of this row's group
    int j0 = __ldg(rowptr + v), jend = __ldg(rowptr + v + 1);
    const uint4* z4 = (const uint4*)z + f4;
    float acc[8] = {0.f, 0.f, 0.f, 0.f, 0.f, 0.f, 0.f, 0.f};

    for (int base = j0; base < jend; base += 4) {
        int2 eloc[EPL];
#pragma unroll
        for (int m = 0; m < EPL; m++) {
            int j = base + f4 * EPL + m;
            j = j < jend ? j : jend - 1;         // clamp (duplicate last edge)
            eloc[m] = __ldg(edge + j);
        }
#pragma unroll
        for (int u = 0; u < 4; u++) {
            int src = rowbase + u / EPL;
            int col = __shfl_sync(~0u, eloc[u % EPL].x, src);
            int wi  = __shfl_sync(~0u, eloc[u % EPL].y, src);
            float w = (base + u < jend) ? __int_as_float(wi) : 0.0f;
            uint4 zz = __ldg(z4 + (size_t)col * LPR);
            fma8(acc, zz, w);
        }
    }

#pragma unroll
    for (int i = 0; i < 8; i++) acc[i] *= scale;
    if (prev) {
        uint4 pv = __ldg((const uint4*)prev + (size_t)v * LPR + f4);
        const __half2* hp = (const __half2*)&pv;
#pragma unroll
        for (int i = 0; i < 4; i++) {
            float2 f = __half22float2(hp[i]);
            acc[2 * i]     -= f.x;
            acc[2 * i + 1] -= f.y;
        }
    }
    uint4 ov;
#pragma unroll
    for (int i = 0; i < 4; i++)
        ((__half2*)&ov)[i] = __floats2half2_rn(acc[2 * i], acc[2 * i + 1]);
    ((uint4*)t)[(size_t)v * LPR + f4] = ov;
}

// ===========================================================================
// Fused 5-term GEMM + bias + ELU. t inputs fp16; W/bias fp32.
// Per-k the 256-vertex t_k tile is cooperatively staged into SMEM (coalesced
// block copy); compute reads rows via broadcast LDS.128. 32 fp32 accumulators
// per thread (lane = out channel, vi = vertex within warp).
// OUTHALF: write __half (layer 1 -> h). Else fp32 (+ factor-4 max pool).
// ===========================================================================
template<int FIN, bool DOPOOL, bool OUTHALF>
__global__ void __launch_bounds__(256) gemm5_kernel(
        const __half* __restrict__ t0, const __half* __restrict__ t1,
        const __half* __restrict__ t2, const __half* __restrict__ t3,
        const __half* __restrict__ t4,
        const float* __restrict__ W, const float* __restrict__ bias,
        void* __restrict__ outv, float* __restrict__ pooled) {
    constexpr int QPR = FIN / 8;                 // uint4 chunks per row
    __shared__ float Wsh[KS * FIN * 32];
    __shared__ uint4 tile[256 * QPR];            // 256 rows of t_k
    __shared__ float bsh[32];
    int tid = threadIdx.x;
    for (int i = tid; i < KS * FIN * 32; i += 256) {
        int fk = i >> 5, o = i & 31;
        int f = fk / KS, k = fk % KS;
        Wsh[(k * FIN + f) * 32 + o] = W[i];
    }
    if (tid < 32) bsh[tid] = bias[tid];
    __syncthreads();

    int warp = tid >> 5, o = tid & 31;
    int vbase = blockIdx.x * 256;
    const __half* ts[KS] = {t0, t1, t2, t3, t4};

    float acc[32];
#pragma unroll
    for (int vi = 0; vi < 32; vi++) acc[vi] = bsh[o];

    for (int k = 0; k < KS; k++) {
        __syncthreads();
        const uint4* src = (const uint4*)(ts[k] + (size_t)vbase * FIN);
#pragma unroll
        for (int i = 0; i < QPR; i++)
            tile[tid + i * 256] = __ldg(src + tid + i * 256);
        __syncthreads();

        const uint4* trow = tile + (size_t)warp * 32 * QPR;
        const float* wk = Wsh + k * FIN * 32 + o;
        for (int vi = 0; vi < 32; vi++) {
            float a0 = 0.0f, a1 = 0.0f;
#pragma unroll
            for (int q = 0; q < QPR; q++) {
                uint4 tv = trow[vi * QPR + q];
                const __half2* hp = (const __half2*)&tv;
#pragma unroll
                for (int i = 0; i < 4; i++) {
                    float2 f = __half22float2(hp[i]);
                    a0 += f.x * wk[(q * 8 + 2 * i) * 32];
                    a1 += f.y * wk[(q * 8 + 2 * i + 1) * 32];
                }
            }
            acc[vi] += a0 + a1;
        }
    }

    float pmax = 0.0f;
    for (int vi = 0; vi < 32; vi++) {
        int v = vbase + warp * 32 + vi;
        float a = acc[vi];
        a = a > 0.0f ? a : expm1f(a);
        if (OUTHALF) {
            float an = __shfl_down_sync(~0u, a, 1);
            if (!(o & 1))
                ((__half2*)((__half*)outv + (size_t)v * 32))[o >> 1] =
                    __floats2half2_rn(a, an);
        } else {
            ((float*)outv)[(size_t)v * 32 + o] = a;
        }
        if (DOPOOL) {
            pmax = (vi & 3) ? fmaxf(pmax, a) : a;
            if ((vi & 3) == 3) pooled[(size_t)(v >> 2) * 32 + o] = pmax;
        }
    }
}

// ===========================================================================
// Host-side layer driver
// ===========================================================================
template<int FIN, bool DOPOOL, bool OUTHALF>
static void run_layer(const __half* xin, const float* W, const float* bias,
                      void* out, float* pooled,
                      __half* t1, __half* t2, __half* t3, __half* t4,
                      const int* rowptr, const int2* edge) {
    constexpr int LPR = FIN / 8;
    const int spmm_blocks = (NV * LPR + 255) / 256;

    spmm_kernel<FIN><<<spmm_blocks, 256>>>(rowptr, edge, xin, nullptr, 1.0f, t1);
    spmm_kernel<FIN><<<spmm_blocks, 256>>>(rowptr, edge, t1,  xin,     2.0f, t2);
    spmm_kernel<FIN><<<spmm_blocks, 256>>>(rowptr, edge, t2,  t1,      2.0f, t3);
    spmm_kernel<FIN><<<spmm_blocks, 256>>>(rowptr, edge, t3,  t2,      2.0f, t4);

    gemm5_kernel<FIN, DOPOOL, OUTHALF><<<NV / 256, 256>>>(
        xin, t1, t2, t3, t4, W, bias, out, pooled);
}

extern "C" void kernel_launch(void* const* d_in, const int* in_sizes, int n_in,
                              void* d_out, int out_size) {
    const float* x    = (const float*)d_in[0];
    const int*   rows = (const int*)  d_in[1];
    const int*   cols = (const int*)  d_in[2];
    const float* vals = (const float*)d_in[3];
    const float* w1   = (const float*)d_in[4];
    const float* b1   = (const float*)d_in[5];
    const float* w2   = (const float*)d_in[6];
    const float* b2   = (const float*)d_in[7];
    int nedges = in_sizes[1];

    float* skip   = (float*)d_out;              // [NV, 32]
    float* pooled = skip + (size_t)NV * 32;     // [NV/4, 32]

    __half *t1, *t2, *t3, *t4, *h, *xh;
    int *deg, *excl, *rowptr, *pos, *bsum;
    int2* edge;
    cudaGetSymbolAddress((void**)&t1, g_t1);
    cudaGetSymbolAddress((void**)&t2, g_t2);
    cudaGetSymbolAddress((void**)&t3, g_t3);
    cudaGetSymbolAddress((void**)&t4, g_t4);
    cudaGetSymbolAddress((void**)&h,  g_h);
    cudaGetSymbolAddress((void**)&xh, g_xh);
    cudaGetSymbolAddress((void**)&deg,    g_deg);
    cudaGetSymbolAddress((void**)&excl,   g_excl);
    cudaGetSymbolAddress((void**)&rowptr, g_rowptr);
    cudaGetSymbolAddress((void**)&pos,    g_pos);
    cudaGetSymbolAddress((void**)&bsum,   g_bsum);
    cudaGetSymbolAddress((void**)&edge,   g_edge);

    const int TPB = 256;
    const int eblocks = (nedges + TPB - 1) / TPB;

    // ---- x -> fp16 ----
    cvt_x_kernel<<<(NV * 2 + TPB - 1) / TPB, TPB>>>(x, xh);

    // ---- CSR build (deg is zero at entry; finalize re-zeroes it) ----
    hist_kernel<<<eblocks, TPB>>>(rows, deg, nedges);
    scan_local_kernel<<<SCAN_BLOCKS, 1024>>>(deg, excl, bsum);
    finalize_kernel<<<(NV + 255) / 256, 256>>>(excl, bsum, rowptr, pos, deg, nedges);
    fill_kernel<<<eblocks, TPB>>>(rows, cols, vals, pos, edge, nedges);

    // ---- Layer 1: ChebConv(16 -> 32) + ELU -> h (fp16) ----
    run_layer<16, false, true>(xh, w1, b1, h, nullptr, t1, t2, t3, t4, rowptr, edge);

    // ---- Layer 2: ChebConv(32 -> 32) + ELU -> skip (fp32), fused pool ----
    run_layer<32, true, false>(h, w2, b2, skip, pooled, t1, t2, t3, t4, rowptr, edge);
}

// round 13
// speedup vs baseline: 1.0882x; 1.0882x over previous
#include <cuda_runtime.h>
#include <cuda_fp16.h>
#include <math.h>

#define NV 786432
#define KS 5
#define EMAX (8 * NV)
#define SCAN_BLOCKS 192   // NV / 4096

// ---- static device scratch (no allocations allowed) ----
__device__ __half g_t1[(size_t)NV * 32];
__device__ __half g_t2[(size_t)NV * 32];
__device__ __half g_t3[(size_t)NV * 32];
__device__ __half g_t4[(size_t)NV * 32];
__device__ __half g_h [(size_t)NV * 32];
__device__ __half g_xh[(size_t)NV * 16];
__device__ int   g_deg[NV];          // zero at entry; finalize re-zeroes for next replay
__device__ int   g_excl[NV];
__device__ int   g_rowptr[NV + 1];
__device__ int   g_pos[NV];
__device__ int   g_bsum[SCAN_BLOCKS];
__device__ int2  g_edge[EMAX];       // (col, float_as_int(val)) interleaved

// ===========================================================================
// CSR build (4 kernels)
// ===========================================================================
__global__ void hist_kernel(const int* __restrict__ rows, int* __restrict__ deg, int nedges) {
    int e = blockIdx.x * blockDim.x + threadIdx.x;
    if (e < nedges) atomicAdd(deg + __ldg(rows + e), 1);
}

__global__ void scan_local_kernel(const int* __restrict__ deg, int* __restrict__ excl,
                                  int* __restrict__ bsum) {
    __shared__ int warp_sums[32];
    int t = threadIdx.x;
    int base = blockIdx.x * 4096 + t * 4;
    int4 d = *(const int4*)(deg + base);
    int tsum = d.x + d.y + d.z + d.w;
    int lane = t & 31, wid = t >> 5;
    int v = tsum;
#pragma unroll
    for (int o = 1; o < 32; o <<= 1) {
        int n = __shfl_up_sync(~0u, v, o);
        if (lane >= o) v += n;
    }
    if (lane == 31) warp_sums[wid] = v;
    __syncthreads();
    if (wid == 0) {
        int ws = warp_sums[lane];
#pragma unroll
        for (int o = 1; o < 32; o <<= 1) {
            int n = __shfl_up_sync(~0u, ws, o);
            if (lane >= o) ws += n;
        }
        warp_sums[lane] = ws;
    }
    __syncthreads();
    int warp_off = (wid == 0) ? 0 : warp_sums[wid - 1];
    int e0 = warp_off + v - tsum;
    excl[base + 0] = e0;
    excl[base + 1] = e0 + d.x;
    excl[base + 2] = e0 + d.x + d.y;
    excl[base + 3] = e0 + d.x + d.y + d.z;
    if (t == 0) bsum[blockIdx.x] = warp_sums[31];
}

__global__ void finalize_kernel(const int* __restrict__ excl, const int* __restrict__ bsum,
                                int* __restrict__ rowptr, int* __restrict__ pos,
                                int* __restrict__ deg, int nedges) {
    __shared__ int s[256];
    int t = threadIdx.x;
    s[t] = (t < SCAN_BLOCKS) ? bsum[t] : 0;
    __syncthreads();
#pragma unroll
    for (int o = 1; o < 256; o <<= 1) {
        int add = (t >= o) ? s[t - o] : 0;
        __syncthreads();
        s[t] += add;
        __syncthreads();
    }
    int i = blockIdx.x * 256 + t;
    if (i < NV) {
        int sb = i >> 12;
        int off = (sb == 0) ? 0 : s[sb - 1];
        int r = excl[i] + off;
        rowptr[i] = r;
        pos[i] = r;
        deg[i] = 0;
        if (i == 0) rowptr[NV] = nedges;
    }
}

__global__ void fill_kernel(const int* __restrict__ rows, const int* __restrict__ cols,
                            const float* __restrict__ vals, int* __restrict__ pos,
                            int2* __restrict__ edge, int nedges) {
    int e = blockIdx.x * blockDim.x + threadIdx.x;
    if (e >= nedges) return;
    int r = __ldg(rows + e);
    int p = atomicAdd(pos + r, 1);
    edge[p] = make_int2(__ldg(cols + e), __float_as_int(__ldg(vals + e)));
}

// x (fp32, 16 ch) -> half
__global__ void cvt_x_kernel(const float* __restrict__ x, __half* __restrict__ xh) {
    int i = blockIdx.x * blockDim.x + threadIdx.x;   // one per 8 elems
    if (i >= NV * 2) return;
    float4 a = ((const float4*)x)[i * 2];
    float4 b = ((const float4*)x)[i * 2 + 1];
    uint4 o;
    ((__half2*)&o)[0] = __floats2half2_rn(a.x, a.y);
    ((__half2*)&o)[1] = __floats2half2_rn(a.z, a.w);
    ((__half2*)&o)[2] = __floats2half2_rn(b.x, b.y);
    ((__half2*)&o)[3] = __floats2half2_rn(b.z, b.w);
    ((uint4*)xh)[i] = o;
}

// ===========================================================================
// Gather SpMM (fp16 features, fp32 accumulate) with fused recurrence:
//   t[v,:] = scale * sum_j val_j * z[col_j,:]  -  (prev ? prev[v,:] : 0)
// LPR = FIN/8 lanes per row (one uint4 = 8 half per lane).
// Edges staged into SMEM once per block (dedup). Exact 4-wide main loop +
// short scalar tail: at the LDG-issue floor, clamped/masked batches waste
// ~19% of z-gather issue slots (measured R11 vs floor), so no wasted loads.
// ===========================================================================
__device__ __forceinline__ void fma8(float* acc, uint4 zz, float w) {
    const __half2* hp = (const __half2*)&zz;
#pragma unroll
    for (int i = 0; i < 4; i++) {
        float2 f = __half22float2(hp[i]);
        acc[2 * i]     += w * f.x;
        acc[2 * i + 1] += w * f.y;
    }
}

template<int FIN>
__global__ void __launch_bounds__(256) spmm_kernel(
        const int* __restrict__ rowptr, const int2* __restrict__ edge,
        const __half* __restrict__ z, const __half* __restrict__ prev,
        float scale, __half* __restrict__ t) {
    constexpr int LPR = FIN / 8;
    constexpr int RPB = 256 / LPR;
    constexpr int CHUNK = 2048;            // edges staged per pass (16 KB)
    __shared__ int2 sedge[CHUNK];
    int tid = threadIdx.x;
    int v0 = blockIdx.x * RPB;
    int v  = v0 + tid / LPR;
    int f4 = tid % LPR;
    int e0 = __ldg(rowptr + v0);
    int e1 = __ldg(rowptr + v0 + RPB);
    int j0 = __ldg(rowptr + v), jend = __ldg(rowptr + v + 1);
    const uint4* z4 = (const uint4*)z + f4;
    float acc[8] = {0.f, 0.f, 0.f, 0.f, 0.f, 0.f, 0.f, 0.f};

    for (int ebase = e0; ebase < e1; ebase += CHUNK) {
        int cnt = min(CHUNK, e1 - ebase);
        if (ebase != e0) __syncthreads();
        for (int i = tid; i < cnt; i += 256)
            sedge[i] = __ldg(edge + ebase + i);    // coalesced, once per edge
        __syncthreads();

        int js = max(j0, ebase), je = min(jend, ebase + cnt);
        int j = js;
        for (; j + 4 <= je; j += 4) {              // exact 4-wide batches
            int2 e[4];
            uint4 zz[4];
#pragma unroll
            for (int u = 0; u < 4; u++) e[u] = sedge[j + u - ebase];
#pragma unroll
            for (int u = 0; u < 4; u++) zz[u] = __ldg(z4 + (size_t)e[u].x * LPR);
#pragma unroll
            for (int u = 0; u < 4; u++) fma8(acc, zz[u], __int_as_float(e[u].y));
        }
        for (; j < je; j++) {                      // <=3 scalar tail, no waste
            int2 e = sedge[j - ebase];
            uint4 zz = __ldg(z4 + (size_t)e.x * LPR);
            fma8(acc, zz, __int_as_float(e.y));
        }
    }

#pragma unroll
    for (int i = 0; i < 8; i++) acc[i] *= scale;
    if (prev) {
        uint4 pv = __ldg((const uint4*)prev + (size_t)v * LPR + f4);
        const __half2* hp = (const __half2*)&pv;
#pragma unroll
        for (int i = 0; i < 4; i++) {
            float2 f = __half22float2(hp[i]);
            acc[2 * i]     -= f.x;
            acc[2 * i + 1] -= f.y;
        }
    }
    uint4 ov;
#pragma unroll
    for (int i = 0; i < 4; i++)
        ((__half2*)&ov)[i] = __floats2half2_rn(acc[2 * i], acc[2 * i + 1]);
    ((uint4*)t)[(size_t)v * LPR + f4] = ov;
}

// ===========================================================================
// Fused 5-term GEMM + bias + ELU. t inputs fp16; W/bias fp32.
// Per-k the 256-vertex t_k tile is cooperatively staged into SMEM (coalesced
// block copy); compute reads rows via broadcast LDS.128. 32 fp32 accumulators
// per thread (lane = out channel, vi = vertex within warp).
// OUTHALF: write __half (layer 1 -> h). Else fp32 (+ factor-4 max pool).
// ===========================================================================
template<int FIN, bool DOPOOL, bool OUTHALF>
__global__ void __launch_bounds__(256) gemm5_kernel(
        const __half* __restrict__ t0, const __half* __restrict__ t1,
        const __half* __restrict__ t2, const __half* __restrict__ t3,
        const __half* __restrict__ t4,
        const float* __restrict__ W, const float* __restrict__ bias,
        void* __restrict__ outv, float* __restrict__ pooled) {
    constexpr int QPR = FIN / 8;                 // uint4 chunks per row
    __shared__ float Wsh[KS * FIN * 32];
    __shared__ uint4 tile[256 * QPR];            // 256 rows of t_k
    __shared__ float bsh[32];
    int tid = threadIdx.x;
    for (int i = tid; i < KS * FIN * 32; i += 256) {
        int fk = i >> 5, o = i & 31;
        int f = fk / KS, k = fk % KS;
        Wsh[(k * FIN + f) * 32 + o] = W[i];
    }
    if (tid < 32) bsh[tid] = bias[tid];
    __syncthreads();

    int warp = tid >> 5, o = tid & 31;
    int vbase = blockIdx.x * 256;
    const __half* ts[KS] = {t0, t1, t2, t3, t4};

    float acc[32];
#pragma unroll
    for (int vi = 0; vi < 32; vi++) acc[vi] = bsh[o];

    for (int k = 0; k < KS; k++) {
        __syncthreads();
        const uint4* src = (const uint4*)(ts[k] + (size_t)vbase * FIN);
#pragma unroll
        for (int i = 0; i < QPR; i++)
            tile[tid + i * 256] = __ldg(src + tid + i * 256);
        __syncthreads();

        const uint4* trow = tile + (size_t)warp * 32 * QPR;
        const float* wk = Wsh + k * FIN * 32 + o;
        for (int vi = 0; vi < 32; vi++) {
            float a0 = 0.0f, a1 = 0.0f;
#pragma unroll
            for (int q = 0; q < QPR; q++) {
                uint4 tv = trow[vi * QPR + q];
                const __half2* hp = (const __half2*)&tv;
#pragma unroll
                for (int i = 0; i < 4; i++) {
                    float2 f = __half22float2(hp[i]);
                    a0 += f.x * wk[(q * 8 + 2 * i) * 32];
                    a1 += f.y * wk[(q * 8 + 2 * i + 1) * 32];
                }
            }
            acc[vi] += a0 + a1;
        }
    }

    float pmax = 0.0f;
    for (int vi = 0; vi < 32; vi++) {
        int v = vbase + warp * 32 + vi;
        float a = acc[vi];
        a = a > 0.0f ? a : expm1f(a);
        if (OUTHALF) {
            float an = __shfl_down_sync(~0u, a, 1);
            if (!(o & 1))
                ((__half2*)((__half*)outv + (size_t)v * 32))[o >> 1] =
                    __floats2half2_rn(a, an);
        } else {
            ((float*)outv)[(size_t)v * 32 + o] = a;
        }
        if (DOPOOL) {
            pmax = (vi & 3) ? fmaxf(pmax, a) : a;
            if ((vi & 3) == 3) pooled[(size_t)(v >> 2) * 32 + o] = pmax;
        }
    }
}

// ===========================================================================
// Host-side layer driver
// ===========================================================================
template<int FIN, bool DOPOOL, bool OUTHALF>
static void run_layer(const __half* xin, const float* W, const float* bias,
                      void* out, float* pooled,
                      __half* t1, __half* t2, __half* t3, __half* t4,
                      const int* rowptr, const int2* edge) {
    constexpr int LPR = FIN / 8;
    constexpr int RPB = 256 / LPR;
    const int spmm_blocks = NV / RPB;

    spmm_kernel<FIN><<<spmm_blocks, 256>>>(rowptr, edge, xin, nullptr, 1.0f, t1);
    spmm_kernel<FIN><<<spmm_blocks, 256>>>(rowptr, edge, t1,  xin,     2.0f, t2);
    spmm_kernel<FIN><<<spmm_blocks, 256>>>(rowptr, edge, t2,  t1,      2.0f, t3);
    spmm_kernel<FIN><<<spmm_blocks, 256>>>(rowptr, edge, t3,  t2,      2.0f, t4);

    gemm5_kernel<FIN, DOPOOL, OUTHALF><<<NV / 256, 256>>>(
        xin, t1, t2, t3, t4, W, bias, out, pooled);
}

extern "C" void kernel_launch(void* const* d_in, const int* in_sizes, int n_in,
                              void* d_out, int out_size) {
    const float* x    = (const float*)d_in[0];
    const int*   rows = (const int*)  d_in[1];
    const int*   cols = (const int*)  d_in[2];
    const float* vals = (const float*)d_in[3];
    const float* w1   = (const float*)d_in[4];
    const float* b1   = (const float*)d_in[5];
    const float* w2   = (const float*)d_in[6];
    const float* b2   = (const float*)d_in[7];
    int nedges = in_sizes[1];

    float* skip   = (float*)d_out;              // [NV, 32]
    float* pooled = skip + (size_t)NV * 32;     // [NV/4, 32]

    __half *t1, *t2, *t3, *t4, *h, *xh;
    int *deg, *excl, *rowptr, *pos, *bsum;
    int2* edge;
    cudaGetSymbolAddress((void**)&t1, g_t1);
    cudaGetSymbolAddress((void**)&t2, g_t2);
    cudaGetSymbolAddress((void**)&t3, g_t3);
    cudaGetSymbolAddress((void**)&t4, g_t4);
    cudaGetSymbolAddress((void**)&h,  g_h);
    cudaGetSymbolAddress((void**)&xh, g_xh);
    cudaGetSymbolAddress((void**)&deg,    g_deg);
    cudaGetSymbolAddress((void**)&excl,   g_excl);
    cudaGetSymbolAddress((void**)&rowptr, g_rowptr);
    cudaGetSymbolAddress((void**)&pos,    g_pos);
    cudaGetSymbolAddress((void**)&bsum,   g_bsum);
    cudaGetSymbolAddress((void**)&edge,   g_edge);

    const int TPB = 256;
    const int eblocks = (nedges + TPB - 1) / TPB;

    // ---- x -> fp16 ----
    cvt_x_kernel<<<(NV * 2 + TPB - 1) / TPB, TPB>>>(x, xh);

    // ---- CSR build (deg is zero at entry; finalize re-zeroes it) ----
    hist_kernel<<<eblocks, TPB>>>(rows, deg, nedges);
    scan_local_kernel<<<SCAN_BLOCKS, 1024>>>(deg, excl, bsum);
    finalize_kernel<<<(NV + 255) / 256, 256>>>(excl, bsum, rowptr, pos, deg, nedges);
    fill_kernel<<<eblocks, TPB>>>(rows, cols, vals, pos, edge, nedges);

    // ---- Layer 1: ChebConv(16 -> 32) + ELU -> h (fp16) ----
    run_layer<16, false, true>(xh, w1, b1, h, nullptr, t1, t2, t3, t4, rowptr, edge);

    // ---- Layer 2: ChebConv(32 -> 32) + ELU -> skip (fp32), fused pool ----
    run_layer<32, true, false>(h, w2, b2, skip, pooled, t1, t2, t3, t4, rowptr, edge);
}